// round 3
// baseline (speedup 1.0000x reference)
#include <cuda_runtime.h>
#include <math.h>

#define Bb 2
#define Nn 1536
#define Dd 1024
#define Hh 16
#define DH 64
#define MR (Bb*Nn)          // 3072 rows
#define SCALE 0.125f        // DH^-0.5

// ---------------- scratch (no runtime allocation allowed) ----------------
__device__ float g_Q[MR * Dd];
__device__ float g_K[MR * Dd];
__device__ float g_V[MR * Dd];
__device__ float g_G1[MR * Dd];
__device__ float g_gate[MR];
__device__ float g_core[MR * Dd];

// ---------------- generic SGEMM: C[M,N] = A[M,K] @ W[K,N] + bias ----------
// 64x64 block tile, BK=16, 256 threads, 4x4 microtile.
__global__ void __launch_bounds__(256) gemm_bias_kernel(
    const float* __restrict__ A, const float* __restrict__ W,
    const float* __restrict__ bias, float* __restrict__ C,
    int M, int K, int Ncols)
{
    __shared__ float As[16 * 64];  // As[k][m]
    __shared__ float Ws[16 * 64];  // Ws[k][n]

    const int tid = threadIdx.x;
    const int tx = tid & 15, ty = tid >> 4;
    const int m0 = blockIdx.y * 64, n0 = blockIdx.x * 64;

    // loader indices
    const int lm  = tid & 63;         // A row within tile
    const int lk4 = (tid >> 6) * 4;   // A k-start (0,4,8,12)
    const int wk  = tid >> 4;         // W k row (0..15)
    const int wn4 = (tid & 15) * 4;   // W n-start

    float acc[4][4];
#pragma unroll
    for (int i = 0; i < 4; i++)
#pragma unroll
        for (int j = 0; j < 4; j++) acc[i][j] = 0.f;

    for (int k0 = 0; k0 < K; k0 += 16) {
        float4 av = *reinterpret_cast<const float4*>(&A[(size_t)(m0 + lm) * K + k0 + lk4]);
        As[(lk4 + 0) * 64 + lm] = av.x;
        As[(lk4 + 1) * 64 + lm] = av.y;
        As[(lk4 + 2) * 64 + lm] = av.z;
        As[(lk4 + 3) * 64 + lm] = av.w;
        *reinterpret_cast<float4*>(&Ws[wk * 64 + wn4]) =
            *reinterpret_cast<const float4*>(&W[(size_t)(k0 + wk) * Ncols + n0 + wn4]);
        __syncthreads();
#pragma unroll
        for (int kk = 0; kk < 16; kk++) {
            float4 a = *reinterpret_cast<const float4*>(&As[kk * 64 + ty * 4]);
            float4 w = *reinterpret_cast<const float4*>(&Ws[kk * 64 + tx * 4]);
            float ar[4] = {a.x, a.y, a.z, a.w};
            float wr[4] = {w.x, w.y, w.z, w.w};
#pragma unroll
            for (int i = 0; i < 4; i++)
#pragma unroll
                for (int j = 0; j < 4; j++) acc[i][j] += ar[i] * wr[j];
        }
        __syncthreads();
    }

#pragma unroll
    for (int i = 0; i < 4; i++) {
        int m = m0 + ty * 4 + i;
        float4 o;
        o.x = acc[i][0] + bias[n0 + tx * 4 + 0];
        o.y = acc[i][1] + bias[n0 + tx * 4 + 1];
        o.z = acc[i][2] + bias[n0 + tx * 4 + 2];
        o.w = acc[i][3] + bias[n0 + tx * 4 + 3];
        *reinterpret_cast<float4*>(&C[(size_t)m * Ncols + n0 + tx * 4]) = o;
    }
}

// ---------------- gate: sigmoid(gelu(G1) @ Wg2 + bg2), one block per row ---
__global__ void __launch_bounds__(128) gate_kernel(
    const float* __restrict__ G1, const float* __restrict__ Wg2,
    const float* __restrict__ bg2, float* __restrict__ gate)
{
    const int row = blockIdx.x;
    const int tid = threadIdx.x;
    float s = 0.f;
#pragma unroll 4
    for (int k = tid; k < Dd; k += 128) {
        float v = G1[(size_t)row * Dd + k];
        float g = 0.5f * v * (1.0f + erff(v * 0.70710678118654752440f));
        s += g * Wg2[k];
    }
    __shared__ float red[128];
    red[tid] = s;
    __syncthreads();
    for (int off = 64; off; off >>= 1) {
        if (tid < off) red[tid] += red[tid + off];
        __syncthreads();
    }
    if (tid == 0) gate[row] = 1.0f / (1.0f + expf(-(red[0] + bg2[0])));
}

// ---------------- attention: block per (b, h, 64-query tile) --------------
// Two passes over causal key tiles. Pass1: running (max, Z) in registers.
// Pass2: exact p = exp(s-m)/Z, entropy -= p*log(p+1e-6), O += P@V.
// SMEM: QT[d][q] (transposed, stride 64), KT (K transposed / V natural,
// stride 64), Ss[q][k] probabilities (stride 65).
#define SS_STRIDE 65
#define ATTN_SMEM ((64*64 + 64*64 + 64*SS_STRIDE) * 4)

__global__ void __launch_bounds__(256) attn_kernel(
    const float* __restrict__ Q, const float* __restrict__ K,
    const float* __restrict__ V, const float* __restrict__ gate,
    float* __restrict__ core, float* __restrict__ ent_out)
{
    extern __shared__ float sm[];
    float* QT = sm;              // [64][64] q transposed: QT[d*64+q]
    float* KT = sm + 4096;       // K transposed (pass S) / V natural (pass PV)
    float* Ss = sm + 8192;       // [64][SS_STRIDE] probabilities

    const int qt = blockIdx.x, h = blockIdx.y, b = blockIdx.z;
    const int tid = threadIdx.x;
    const int tx = tid & 15, ty = tid >> 4;
    const int q0 = qt * 64;
    const int hoff = h * DH;
    const int rowbase = b * Nn;

    // loader indices: 16 contiguous floats per thread from one row
    const int lr = tid >> 2;
    const int lc = (tid & 3) * 16;

    // ---- load Q tile transposed ----
    {
        const float* src = &Q[(size_t)(rowbase + q0 + lr) * Dd + hoff + lc];
#pragma unroll
        for (int j = 0; j < 16; j += 4) {
            float4 v = *reinterpret_cast<const float4*>(src + j);
            QT[(lc + j + 0) * 64 + lr] = v.x;
            QT[(lc + j + 1) * 64 + lr] = v.y;
            QT[(lc + j + 2) * 64 + lr] = v.z;
            QT[(lc + j + 3) * 64 + lr] = v.w;
        }
    }

    float mrow[4], Zrow[4];
#pragma unroll
    for (int i = 0; i < 4; i++) { mrow[i] = -1e30f; Zrow[i] = 0.f; }

    // ================= PASS 1: max & Z =================
    for (int kt = 0; kt <= qt; kt++) {
        {   // load K tile transposed
            const float* src = &K[(size_t)(rowbase + kt * 64 + lr) * Dd + hoff + lc];
#pragma unroll
            for (int j = 0; j < 16; j += 4) {
                float4 v = *reinterpret_cast<const float4*>(src + j);
                KT[(lc + j + 0) * 64 + lr] = v.x;
                KT[(lc + j + 1) * 64 + lr] = v.y;
                KT[(lc + j + 2) * 64 + lr] = v.z;
                KT[(lc + j + 3) * 64 + lr] = v.w;
            }
        }
        __syncthreads();

        float s[4][4];
#pragma unroll
        for (int i = 0; i < 4; i++)
#pragma unroll
            for (int j = 0; j < 4; j++) s[i][j] = 0.f;
#pragma unroll 16
        for (int d = 0; d < 64; d++) {
            float4 qv = *reinterpret_cast<const float4*>(&QT[d * 64 + ty * 4]);
            float4 kv = *reinterpret_cast<const float4*>(&KT[d * 64 + tx * 4]);
            float qa[4] = {qv.x, qv.y, qv.z, qv.w};
            float ka[4] = {kv.x, kv.y, kv.z, kv.w};
#pragma unroll
            for (int i = 0; i < 4; i++)
#pragma unroll
                for (int j = 0; j < 4; j++) s[i][j] += qa[i] * ka[j];
        }

        const bool diag = (kt == qt);
#pragma unroll
        for (int i = 0; i < 4; i++) {
            const int qi = q0 + ty * 4 + i;
#pragma unroll
            for (int j = 0; j < 4; j++) {
                float v = s[i][j] * SCALE;
                if (diag && (kt * 64 + tx * 4 + j) > qi) v = -1e30f;
                s[i][j] = v;
            }
            float tm = fmaxf(fmaxf(s[i][0], s[i][1]), fmaxf(s[i][2], s[i][3]));
#pragma unroll
            for (int off = 8; off; off >>= 1)
                tm = fmaxf(tm, __shfl_xor_sync(0xffffffffu, tm, off, 16));
            float nm = fmaxf(mrow[i], tm);
            float es = expf(s[i][0] - nm) + expf(s[i][1] - nm) +
                       expf(s[i][2] - nm) + expf(s[i][3] - nm);
#pragma unroll
            for (int off = 8; off; off >>= 1)
                es += __shfl_xor_sync(0xffffffffu, es, off, 16);
            Zrow[i] = Zrow[i] * expf(mrow[i] - nm) + es;
            mrow[i] = nm;
        }
        __syncthreads();
    }

    float invZ[4], entAcc[4], o[4][4];
#pragma unroll
    for (int i = 0; i < 4; i++) {
        invZ[i] = 1.0f / Zrow[i];
        entAcc[i] = 0.f;
#pragma unroll
        for (int j = 0; j < 4; j++) o[i][j] = 0.f;
    }

    // ================= PASS 2: exact p, entropy, PV =================
    for (int kt = 0; kt <= qt; kt++) {
        {   // K tile transposed
            const float* src = &K[(size_t)(rowbase + kt * 64 + lr) * Dd + hoff + lc];
#pragma unroll
            for (int j = 0; j < 16; j += 4) {
                float4 v = *reinterpret_cast<const float4*>(src + j);
                KT[(lc + j + 0) * 64 + lr] = v.x;
                KT[(lc + j + 1) * 64 + lr] = v.y;
                KT[(lc + j + 2) * 64 + lr] = v.z;
                KT[(lc + j + 3) * 64 + lr] = v.w;
            }
        }
        __syncthreads();

        float s[4][4];
#pragma unroll
        for (int i = 0; i < 4; i++)
#pragma unroll
            for (int j = 0; j < 4; j++) s[i][j] = 0.f;
#pragma unroll 16
        for (int d = 0; d < 64; d++) {
            float4 qv = *reinterpret_cast<const float4*>(&QT[d * 64 + ty * 4]);
            float4 kv = *reinterpret_cast<const float4*>(&KT[d * 64 + tx * 4]);
            float qa[4] = {qv.x, qv.y, qv.z, qv.w};
            float ka[4] = {kv.x, kv.y, kv.z, kv.w};
#pragma unroll
            for (int i = 0; i < 4; i++)
#pragma unroll
                for (int j = 0; j < 4; j++) s[i][j] += qa[i] * ka[j];
        }

        const bool diag = (kt == qt);
#pragma unroll
        for (int i = 0; i < 4; i++) {
            const int qi = q0 + ty * 4 + i;
#pragma unroll
            for (int j = 0; j < 4; j++) {
                float v = s[i][j] * SCALE;
                if (diag && (kt * 64 + tx * 4 + j) > qi) v = -1e30f;
                float p = expf(v - mrow[i]) * invZ[i];
                entAcc[i] -= p * logf(p + 1e-6f);
                Ss[(ty * 4 + i) * SS_STRIDE + tx * 4 + j] = p;
            }
        }
        __syncthreads();

        {   // V tile, natural layout [k][d]
            const float* src = &V[(size_t)(rowbase + kt * 64 + lr) * Dd + hoff + lc];
#pragma unroll
            for (int j = 0; j < 16; j += 4) {
                *reinterpret_cast<float4*>(&KT[lr * 64 + lc + j]) =
                    *reinterpret_cast<const float4*>(src + j);
            }
        }
        __syncthreads();

#pragma unroll 8
        for (int k = 0; k < 64; k++) {
            float pa[4];
#pragma unroll
            for (int i = 0; i < 4; i++) pa[i] = Ss[(ty * 4 + i) * SS_STRIDE + k];
            float4 vv = *reinterpret_cast<const float4*>(&KT[k * 64 + tx * 4]);
            float va[4] = {vv.x, vv.y, vv.z, vv.w};
#pragma unroll
            for (int i = 0; i < 4; i++)
#pragma unroll
                for (int j = 0; j < 4; j++) o[i][j] += pa[i] * va[j];
        }
        __syncthreads();
    }

    // ---- write entropy (row-reduced across tx) and gated output ----
#pragma unroll
    for (int i = 0; i < 4; i++) {
        float e = entAcc[i];
#pragma unroll
        for (int off = 8; off; off >>= 1)
            e += __shfl_xor_sync(0xffffffffu, e, off, 16);
        if (tx == 0)
            ent_out[((size_t)(b * Hh + h)) * Nn + q0 + ty * 4 + i] = e;
    }
#pragma unroll
    for (int i = 0; i < 4; i++) {
        const int qi = q0 + ty * 4 + i;
        const float g = gate[rowbase + qi];
        float4 ov;
        ov.x = o[i][0] * g; ov.y = o[i][1] * g;
        ov.z = o[i][2] * g; ov.w = o[i][3] * g;
        *reinterpret_cast<float4*>(&core[(size_t)(rowbase + qi) * Dd + hoff + tx * 4]) = ov;
    }
}

// ---------------- launch ----------------
extern "C" void kernel_launch(void* const* d_in, const int* in_sizes, int n_in,
                              void* d_out, int out_size)
{
    const float* x   = (const float*)d_in[0];
    // d_in[1] = attn_bias (pure causal; implemented analytically)
    const float* Wq  = (const float*)d_in[2];
    const float* bq  = (const float*)d_in[3];
    const float* Wk  = (const float*)d_in[4];
    const float* bk  = (const float*)d_in[5];
    const float* Wv  = (const float*)d_in[6];
    const float* bv  = (const float*)d_in[7];
    const float* Wg1 = (const float*)d_in[8];
    const float* bg1 = (const float*)d_in[9];
    const float* Wg2 = (const float*)d_in[10];
    const float* bg2 = (const float*)d_in[11];
    const float* Wo  = (const float*)d_in[12];
    const float* bo  = (const float*)d_in[13];

    float* out = (float*)d_out;                        // [B,N,D]
    float* ent = out + (size_t)Bb * Nn * Dd;           // [B,H,N]

    float *Qp, *Kp, *Vp, *G1p, *gp, *cp;
    cudaGetSymbolAddress((void**)&Qp,  g_Q);
    cudaGetSymbolAddress((void**)&Kp,  g_K);
    cudaGetSymbolAddress((void**)&Vp,  g_V);
    cudaGetSymbolAddress((void**)&G1p, g_G1);
    cudaGetSymbolAddress((void**)&gp,  g_gate);
    cudaGetSymbolAddress((void**)&cp,  g_core);

    dim3 gg(Dd / 64, MR / 64);
    gemm_bias_kernel<<<gg, 256>>>(x, Wq,  bq,  Qp,  MR, Dd, Dd);
    gemm_bias_kernel<<<gg, 256>>>(x, Wk,  bk,  Kp,  MR, Dd, Dd);
    gemm_bias_kernel<<<gg, 256>>>(x, Wv,  bv,  Vp,  MR, Dd, Dd);
    gemm_bias_kernel<<<gg, 256>>>(x, Wg1, bg1, G1p, MR, Dd, Dd);

    gate_kernel<<<MR, 128>>>(G1p, Wg2, bg2, gp);

    cudaFuncSetAttribute(attn_kernel,
                         cudaFuncAttributeMaxDynamicSharedMemorySize, ATTN_SMEM);
    attn_kernel<<<dim3(Nn / 64, Hh, Bb), 256, ATTN_SMEM>>>(Qp, Kp, Vp, gp, cp, ent);

    gemm_bias_kernel<<<gg, 256>>>(cp, Wo, bo, out, MR, Dd, Dd);
}

// round 5
// speedup vs baseline: 1.1905x; 1.1905x over previous
#include <cuda_runtime.h>
#include <math.h>

#define Bb 2
#define Nn 1536
#define Dd 1024
#define Hh 16
#define DH 64
#define MR (Bb*Nn)          // 3072 rows
#define SCALE 0.125f        // DH^-0.5
#define NT (Nn/64)          // 24 key/query tiles
#define TILE_PAIRS (NT*(NT+1)/2)   // 300 causal tile pairs

// ---------------- scratch (no runtime allocation allowed) ----------------
__device__ float g_Q[MR * Dd];
__device__ float g_K[MR * Dd];
__device__ float g_V[MR * Dd];
__device__ float g_G1[MR * Dd];
__device__ float g_gate[MR];
__device__ float g_core[MR * Dd];
__device__ float g_S[(size_t)Bb * Hh * TILE_PAIRS * 64 * 64];  // 157MB score cache

// ---------------- SGEMM: C[M,N] = A[M,K] @ W[K,N] + bias ------------------
// 128x128 block tile, BK=16, 256 threads, 8x8 microtile, double-buffered
// smem with global->register prefetch overlapped with compute.
__global__ void __launch_bounds__(256, 2) gemm_bias_kernel(
    const float* __restrict__ A, const float* __restrict__ W,
    const float* __restrict__ bias, float* __restrict__ C,
    int M, int K, int Ncols)
{
    __shared__ float As[2][16 * 128];  // As[k][m]
    __shared__ float Bs[2][16 * 128];  // Bs[k][n]

    const int tid = threadIdx.x;
    const int tx = tid & 15, ty = tid >> 4;
    const int m0 = blockIdx.y * 128, n0 = blockIdx.x * 128;

    // A loader: row ar (0..127), two float4 along k at quad akq and akq+2
    const int ar  = tid & 127;
    const int akq = tid >> 7;            // 0 or 1
    // B loader: k rows bkr and bkr+8, n quad bn4
    const int bkr = tid >> 5;            // 0..7
    const int bn4 = (tid & 31) * 4;

    const float* Aptr = A + (size_t)(m0 + ar) * K;
    const float* Wptr = W + n0 + bn4;

    float4 a0, a1, b0, b1;
    // prologue: load tile 0
    a0 = *reinterpret_cast<const float4*>(Aptr + akq * 4);
    a1 = *reinterpret_cast<const float4*>(Aptr + (akq + 2) * 4);
    b0 = *reinterpret_cast<const float4*>(Wptr + (size_t)bkr * Ncols);
    b1 = *reinterpret_cast<const float4*>(Wptr + (size_t)(bkr + 8) * Ncols);

    float acc[8][8];
#pragma unroll
    for (int i = 0; i < 8; i++)
#pragma unroll
        for (int j = 0; j < 8; j++) acc[i][j] = 0.f;

    // store tile 0 to smem buffer 0
    {
        As[0][(akq * 4 + 0) * 128 + ar] = a0.x;
        As[0][(akq * 4 + 1) * 128 + ar] = a0.y;
        As[0][(akq * 4 + 2) * 128 + ar] = a0.z;
        As[0][(akq * 4 + 3) * 128 + ar] = a0.w;
        As[0][((akq + 2) * 4 + 0) * 128 + ar] = a1.x;
        As[0][((akq + 2) * 4 + 1) * 128 + ar] = a1.y;
        As[0][((akq + 2) * 4 + 2) * 128 + ar] = a1.z;
        As[0][((akq + 2) * 4 + 3) * 128 + ar] = a1.w;
        *reinterpret_cast<float4*>(&Bs[0][bkr * 128 + bn4]) = b0;
        *reinterpret_cast<float4*>(&Bs[0][(bkr + 8) * 128 + bn4]) = b1;
    }

    const int nIt = K / 16;
    int buf = 0;

    for (int it = 0; it < nIt; it++) {
        __syncthreads();
        // prefetch next tile into registers
        if (it + 1 < nIt) {
            const float* Ap = Aptr + (it + 1) * 16;
            a0 = *reinterpret_cast<const float4*>(Ap + akq * 4);
            a1 = *reinterpret_cast<const float4*>(Ap + (akq + 2) * 4);
            const float* Wp = Wptr + (size_t)((it + 1) * 16 + bkr) * Ncols;
            b0 = *reinterpret_cast<const float4*>(Wp);
            b1 = *reinterpret_cast<const float4*>(Wp + (size_t)8 * Ncols);
        }
        // compute on current buffer
        const float4* As4 = reinterpret_cast<const float4*>(As[buf]);
        const float4* Bs4 = reinterpret_cast<const float4*>(Bs[buf]);
#pragma unroll
        for (int kk = 0; kk < 16; kk++) {
            float4 xa0 = As4[kk * 32 + ty * 2];
            float4 xa1 = As4[kk * 32 + ty * 2 + 1];
            float4 yb0 = Bs4[kk * 32 + tx * 2];
            float4 yb1 = Bs4[kk * 32 + tx * 2 + 1];
            float av[8] = {xa0.x, xa0.y, xa0.z, xa0.w, xa1.x, xa1.y, xa1.z, xa1.w};
            float bv[8] = {yb0.x, yb0.y, yb0.z, yb0.w, yb1.x, yb1.y, yb1.z, yb1.w};
#pragma unroll
            for (int i = 0; i < 8; i++)
#pragma unroll
                for (int j = 0; j < 8; j++) acc[i][j] += av[i] * bv[j];
        }
        // write prefetched tile to other buffer
        if (it + 1 < nIt) {
            int nb = buf ^ 1;
            As[nb][(akq * 4 + 0) * 128 + ar] = a0.x;
            As[nb][(akq * 4 + 1) * 128 + ar] = a0.y;
            As[nb][(akq * 4 + 2) * 128 + ar] = a0.z;
            As[nb][(akq * 4 + 3) * 128 + ar] = a0.w;
            As[nb][((akq + 2) * 4 + 0) * 128 + ar] = a1.x;
            As[nb][((akq + 2) * 4 + 1) * 128 + ar] = a1.y;
            As[nb][((akq + 2) * 4 + 2) * 128 + ar] = a1.z;
            As[nb][((akq + 2) * 4 + 3) * 128 + ar] = a1.w;
            *reinterpret_cast<float4*>(&Bs[nb][bkr * 128 + bn4]) = b0;
            *reinterpret_cast<float4*>(&Bs[nb][(bkr + 8) * 128 + bn4]) = b1;
            buf = nb;
        }
    }

    // epilogue: bias + store
    float bb[8];
#pragma unroll
    for (int j = 0; j < 8; j++) bb[j] = bias[n0 + tx * 8 + j];
#pragma unroll
    for (int i = 0; i < 8; i++) {
        int m = m0 + ty * 8 + i;
        float* Cp = &C[(size_t)m * Ncols + n0 + tx * 8];
        float4 o0, o1;
        o0.x = acc[i][0] + bb[0]; o0.y = acc[i][1] + bb[1];
        o0.z = acc[i][2] + bb[2]; o0.w = acc[i][3] + bb[3];
        o1.x = acc[i][4] + bb[4]; o1.y = acc[i][5] + bb[5];
        o1.z = acc[i][6] + bb[6]; o1.w = acc[i][7] + bb[7];
        *reinterpret_cast<float4*>(Cp)     = o0;
        *reinterpret_cast<float4*>(Cp + 4) = o1;
    }
}

// ---------------- gate: sigmoid(gelu(G1) @ Wg2 + bg2), one block per row ---
__global__ void __launch_bounds__(128) gate_kernel(
    const float* __restrict__ G1, const float* __restrict__ Wg2,
    const float* __restrict__ bg2, float* __restrict__ gate)
{
    const int row = blockIdx.x;
    const int tid = threadIdx.x;
    float s = 0.f;
#pragma unroll 4
    for (int k = tid; k < Dd; k += 128) {
        float v = G1[(size_t)row * Dd + k];
        float g = 0.5f * v * (1.0f + erff(v * 0.70710678118654752440f));
        s += g * Wg2[k];
    }
    __shared__ float red[128];
    red[tid] = s;
    __syncthreads();
    for (int off = 64; off; off >>= 1) {
        if (tid < off) red[tid] += red[tid + off];
        __syncthreads();
    }
    if (tid == 0) gate[row] = 1.0f / (1.0f + expf(-(red[0] + bg2[0])));
}

// ---------------- attention: block per (b, h, 64-query tile) --------------
// Pass1: QK^T tile -> scaled+masked scores cached to g_S; running (max, Z).
// Pass2: reload scores from g_S (no QK recompute), exact p, entropy, P@V.
#define SS_STRIDE 65
#define ATTN_SMEM ((64*64 + 64*64 + 64*SS_STRIDE) * 4)

__global__ void __launch_bounds__(256) attn_kernel(
    const float* __restrict__ Q, const float* __restrict__ K,
    const float* __restrict__ V, const float* __restrict__ gate,
    float* __restrict__ core, float* __restrict__ ent_out)
{
    extern __shared__ float sm[];
    float* QT = sm;              // [64][64] q transposed: QT[d*64+q]
    float* KT = sm + 4096;       // K transposed (pass1) / V natural (pass2)
    float* Ss = sm + 8192;       // [64][SS_STRIDE] probabilities

    const int qt = blockIdx.x, h = blockIdx.y, b = blockIdx.z;
    const int tid = threadIdx.x;
    const int tx = tid & 15, ty = tid >> 4;
    const int q0 = qt * 64;
    const int hoff = h * DH;
    const int rowbase = b * Nn;
    const size_t headbase = ((size_t)(b * Hh + h) * TILE_PAIRS + (size_t)qt * (qt + 1) / 2) * 4096;

    // loader indices: 16 contiguous floats per thread from one row
    const int lr = tid >> 2;
    const int lc = (tid & 3) * 16;

    // ---- load Q tile transposed ----
    {
        const float* src = &Q[(size_t)(rowbase + q0 + lr) * Dd + hoff + lc];
#pragma unroll
        for (int j = 0; j < 16; j += 4) {
            float4 v = *reinterpret_cast<const float4*>(src + j);
            QT[(lc + j + 0) * 64 + lr] = v.x;
            QT[(lc + j + 1) * 64 + lr] = v.y;
            QT[(lc + j + 2) * 64 + lr] = v.z;
            QT[(lc + j + 3) * 64 + lr] = v.w;
        }
    }

    float mrow[4], Zrow[4];
#pragma unroll
    for (int i = 0; i < 4; i++) { mrow[i] = -1e30f; Zrow[i] = 0.f; }

    // ================= PASS 1: scores -> g_S, running max & Z =============
    for (int kt = 0; kt <= qt; kt++) {
        {   // load K tile transposed
            const float* src = &K[(size_t)(rowbase + kt * 64 + lr) * Dd + hoff + lc];
#pragma unroll
            for (int j = 0; j < 16; j += 4) {
                float4 v = *reinterpret_cast<const float4*>(src + j);
                KT[(lc + j + 0) * 64 + lr] = v.x;
                KT[(lc + j + 1) * 64 + lr] = v.y;
                KT[(lc + j + 2) * 64 + lr] = v.z;
                KT[(lc + j + 3) * 64 + lr] = v.w;
            }
        }
        __syncthreads();

        float s[4][4];
#pragma unroll
        for (int i = 0; i < 4; i++)
#pragma unroll
            for (int j = 0; j < 4; j++) s[i][j] = 0.f;
#pragma unroll 16
        for (int d = 0; d < 64; d++) {
            float4 qv = *reinterpret_cast<const float4*>(&QT[d * 64 + ty * 4]);
            float4 kv = *reinterpret_cast<const float4*>(&KT[d * 64 + tx * 4]);
            float qa[4] = {qv.x, qv.y, qv.z, qv.w};
            float ka[4] = {kv.x, kv.y, kv.z, kv.w};
#pragma unroll
            for (int i = 0; i < 4; i++)
#pragma unroll
                for (int j = 0; j < 4; j++) s[i][j] += qa[i] * ka[j];
        }

        const bool diag = (kt == qt);
        float* Sg = &g_S[headbase + (size_t)kt * 4096];
#pragma unroll
        for (int i = 0; i < 4; i++) {
            const int qi = q0 + ty * 4 + i;
#pragma unroll
            for (int j = 0; j < 4; j++) {
                float v = s[i][j] * SCALE;
                if (diag && (kt * 64 + tx * 4 + j) > qi) v = -1e30f;
                s[i][j] = v;
            }
            float4 sv = make_float4(s[i][0], s[i][1], s[i][2], s[i][3]);
            *reinterpret_cast<float4*>(&Sg[(ty * 4 + i) * 64 + tx * 4]) = sv;

            float tm = fmaxf(fmaxf(s[i][0], s[i][1]), fmaxf(s[i][2], s[i][3]));
#pragma unroll
            for (int off = 8; off; off >>= 1)
                tm = fmaxf(tm, __shfl_xor_sync(0xffffffffu, tm, off, 16));
            float nm = fmaxf(mrow[i], tm);
            float es = __expf(s[i][0] - nm) + __expf(s[i][1] - nm) +
                       __expf(s[i][2] - nm) + __expf(s[i][3] - nm);
#pragma unroll
            for (int off = 8; off; off >>= 1)
                es += __shfl_xor_sync(0xffffffffu, es, off, 16);
            Zrow[i] = Zrow[i] * __expf(mrow[i] - nm) + es;
            mrow[i] = nm;
        }
        __syncthreads();
    }

    float invZ[4], entAcc[4], o[4][4];
#pragma unroll
    for (int i = 0; i < 4; i++) {
        invZ[i] = 1.0f / Zrow[i];
        entAcc[i] = 0.f;
#pragma unroll
        for (int j = 0; j < 4; j++) o[i][j] = 0.f;
    }

    // ================= PASS 2: reload S, exact p, entropy, PV =============
    for (int kt = 0; kt <= qt; kt++) {
        const float* Sg = &g_S[headbase + (size_t)kt * 4096];
#pragma unroll
        for (int i = 0; i < 4; i++) {
            float4 sv = *reinterpret_cast<const float4*>(&Sg[(ty * 4 + i) * 64 + tx * 4]);
            float sr[4] = {sv.x, sv.y, sv.z, sv.w};
#pragma unroll
            for (int j = 0; j < 4; j++) {
                float p = __expf(sr[j] - mrow[i]) * invZ[i];
                entAcc[i] -= p * logf(p + 1e-6f);
                Ss[(ty * 4 + i) * SS_STRIDE + tx * 4 + j] = p;
            }
        }

        {   // V tile, natural layout [k][d]
            const float* src = &V[(size_t)(rowbase + kt * 64 + lr) * Dd + hoff + lc];
#pragma unroll
            for (int j = 0; j < 16; j += 4) {
                *reinterpret_cast<float4*>(&KT[lr * 64 + lc + j]) =
                    *reinterpret_cast<const float4*>(src + j);
            }
        }
        __syncthreads();

#pragma unroll 8
        for (int k = 0; k < 64; k++) {
            float pa[4];
#pragma unroll
            for (int i = 0; i < 4; i++) pa[i] = Ss[(ty * 4 + i) * SS_STRIDE + k];
            float4 vv = *reinterpret_cast<const float4*>(&KT[k * 64 + tx * 4]);
            float va[4] = {vv.x, vv.y, vv.z, vv.w};
#pragma unroll
            for (int i = 0; i < 4; i++)
#pragma unroll
                for (int j = 0; j < 4; j++) o[i][j] += pa[i] * va[j];
        }
        __syncthreads();
    }

    // ---- write entropy (row-reduced across tx) and gated output ----
#pragma unroll
    for (int i = 0; i < 4; i++) {
        float e = entAcc[i];
#pragma unroll
        for (int off = 8; off; off >>= 1)
            e += __shfl_xor_sync(0xffffffffu, e, off, 16);
        if (tx == 0)
            ent_out[((size_t)(b * Hh + h)) * Nn + q0 + ty * 4 + i] = e;
    }
#pragma unroll
    for (int i = 0; i < 4; i++) {
        const int qi = q0 + ty * 4 + i;
        const float g = gate[rowbase + qi];
        float4 ov;
        ov.x = o[i][0] * g; ov.y = o[i][1] * g;
        ov.z = o[i][2] * g; ov.w = o[i][3] * g;
        *reinterpret_cast<float4*>(&core[(size_t)(rowbase + qi) * Dd + hoff + tx * 4]) = ov;
    }
}

// ---------------- launch ----------------
extern "C" void kernel_launch(void* const* d_in, const int* in_sizes, int n_in,
                              void* d_out, int out_size)
{
    const float* x   = (const float*)d_in[0];
    // d_in[1] = attn_bias (pure causal; implemented analytically)
    const float* Wq  = (const float*)d_in[2];
    const float* bq  = (const float*)d_in[3];
    const float* Wk  = (const float*)d_in[4];
    const float* bk  = (const float*)d_in[5];
    const float* Wv  = (const float*)d_in[6];
    const float* bv  = (const float*)d_in[7];
    const float* Wg1 = (const float*)d_in[8];
    const float* bg1 = (const float*)d_in[9];
    const float* Wg2 = (const float*)d_in[10];
    const float* bg2 = (const float*)d_in[11];
    const float* Wo  = (const float*)d_in[12];
    const float* bo  = (const float*)d_in[13];

    float* out = (float*)d_out;                        // [B,N,D]
    float* ent = out + (size_t)Bb * Nn * Dd;           // [B,H,N]

    float *Qp, *Kp, *Vp, *G1p, *gp, *cp;
    cudaGetSymbolAddress((void**)&Qp,  g_Q);
    cudaGetSymbolAddress((void**)&Kp,  g_K);
    cudaGetSymbolAddress((void**)&Vp,  g_V);
    cudaGetSymbolAddress((void**)&G1p, g_G1);
    cudaGetSymbolAddress((void**)&gp,  g_gate);
    cudaGetSymbolAddress((void**)&cp,  g_core);

    dim3 gg(Dd / 128, MR / 128);
    gemm_bias_kernel<<<gg, 256>>>(x, Wq,  bq,  Qp,  MR, Dd, Dd);
    gemm_bias_kernel<<<gg, 256>>>(x, Wk,  bk,  Kp,  MR, Dd, Dd);
    gemm_bias_kernel<<<gg, 256>>>(x, Wv,  bv,  Vp,  MR, Dd, Dd);
    gemm_bias_kernel<<<gg, 256>>>(x, Wg1, bg1, G1p, MR, Dd, Dd);

    gate_kernel<<<MR, 128>>>(G1p, Wg2, bg2, gp);

    cudaFuncSetAttribute(attn_kernel,
                         cudaFuncAttributeMaxDynamicSharedMemorySize, ATTN_SMEM);
    attn_kernel<<<dim3(Nn / 64, Hh, Bb), 256, ATTN_SMEM>>>(Qp, Kp, Vp, gp, cp, ent);

    gemm_bias_kernel<<<gg, 256>>>(cp, Wo, bo, out, MR, Dd, Dd);
}

// round 10
// speedup vs baseline: 2.0381x; 1.7119x over previous
#include <cuda_runtime.h>
#include <cuda_bf16.h>
#include <math.h>
#include <stdint.h>

#define Bb 2
#define Nn 1536
#define Dd 1024
#define Hh 16
#define DH 64
#define MR (Bb*Nn)          // 3072 rows
#define SCALE 0.125f        // DH^-0.5
#define NT (Nn/64)          // 24 key/query tiles
#define TILE_PAIRS (NT*(NT+1)/2)   // 300 causal tile pairs

// ---------------- scratch (no runtime allocation allowed) ----------------
__device__ float g_Q[MR * Dd];
__device__ float g_K[MR * Dd];
__device__ float g_V[MR * Dd];
__device__ float g_G1[MR * Dd];
__device__ float g_gate[MR];
__device__ float g_core[MR * Dd];
__device__ float g_S[(size_t)Bb * Hh * TILE_PAIRS * 64 * 64];  // score cache
__device__ __align__(128) __nv_bfloat16 g_Ahi[(size_t)MR * Dd];
__device__ __align__(128) __nv_bfloat16 g_Alo[(size_t)MR * Dd];
__device__ __align__(128) __nv_bfloat16 g_Wthi[(size_t)5 * Dd * Dd]; // [N,K] transposed
__device__ __align__(128) __nv_bfloat16 g_Wtlo[(size_t)5 * Dd * Dd];

// ======================= helpers (base compute_103 only) ==================
__device__ __forceinline__ uint32_t s2u(const void* p) {
    uint32_t a;
    asm("{ .reg .u64 t; cvta.to.shared.u64 t, %1; cvt.u32.u64 %0, t; }"
        : "=r"(a) : "l"(p));
    return a;
}
#define CP16(dst, src) \
    asm volatile("cp.async.cg.shared.global [%0], [%1], 16;" \
        :: "r"((uint32_t)(dst)), "l"(src) : "memory")
#define CPCOMMIT() asm volatile("cp.async.commit_group;" ::: "memory")
#define CPWAIT1()  asm volatile("cp.async.wait_group 1;" ::: "memory")
#define CPWAIT0()  asm volatile("cp.async.wait_group 0;" ::: "memory")
#define SWZ(o) ((o) ^ (((o) >> 3) & 0x70))

#define LDSM4(r, a) \
    asm volatile("ldmatrix.sync.aligned.m8n8.x4.shared.b16 {%0,%1,%2,%3}, [%4];" \
        : "=r"((r)[0]), "=r"((r)[1]), "=r"((r)[2]), "=r"((r)[3]) : "r"(a))

__device__ __forceinline__ void mma_bf16(float* acc, const uint32_t* a,
                                         uint32_t b0, uint32_t b1) {
    asm volatile("mma.sync.aligned.m16n8k16.row.col.f32.bf16.bf16.f32 "
        "{%0,%1,%2,%3}, {%4,%5,%6,%7}, {%8,%9}, {%0,%1,%2,%3};"
        : "+f"(acc[0]), "+f"(acc[1]), "+f"(acc[2]), "+f"(acc[3])
        : "r"(a[0]), "r"(a[1]), "r"(a[2]), "r"(a[3]), "r"(b0), "r"(b1));
}

// ================== hi/lo split of activations (elementwise) ==============
__global__ void __launch_bounds__(256) asplit_kernel(
    const float* __restrict__ src, __nv_bfloat16* __restrict__ hi,
    __nv_bfloat16* __restrict__ lo)
{
    size_t i = ((size_t)blockIdx.x * 256 + threadIdx.x) * 4;
    float4 v = *reinterpret_cast<const float4*>(src + i);
    float vv[4] = {v.x, v.y, v.z, v.w};
    __nv_bfloat16 h[4], l[4];
#pragma unroll
    for (int j = 0; j < 4; j++) {
        h[j] = __float2bfloat16(vv[j]);
        l[j] = __float2bfloat16(vv[j] - __bfloat162float(h[j]));
    }
    *reinterpret_cast<__nv_bfloat162*>(hi + i)     = __nv_bfloat162(h[0], h[1]);
    *reinterpret_cast<__nv_bfloat162*>(hi + i + 2) = __nv_bfloat162(h[2], h[3]);
    *reinterpret_cast<__nv_bfloat162*>(lo + i)     = __nv_bfloat162(l[0], l[1]);
    *reinterpret_cast<__nv_bfloat162*>(lo + i + 2) = __nv_bfloat162(l[2], l[3]);
}

// ============ weight transpose + hi/lo split: W[K,N] -> Wt[N,K] ===========
__global__ void __launch_bounds__(256) wsplit_kernel(
    const float* __restrict__ W0, const float* __restrict__ W1,
    const float* __restrict__ W2, const float* __restrict__ W3,
    const float* __restrict__ W4)
{
    const int z = blockIdx.z;
    const float* W = (z == 0) ? W0 : (z == 1) ? W1 : (z == 2) ? W2 : (z == 3) ? W3 : W4;
    __shared__ float t[32][33];
    const int n0 = blockIdx.x * 32, k0 = blockIdx.y * 32;
    const int tx = threadIdx.x & 31, ty = threadIdx.x >> 5;   // 32 x 8
#pragma unroll
    for (int i = 0; i < 4; i++)
        t[ty + i * 8][tx] = W[(size_t)(k0 + ty + i * 8) * Dd + n0 + tx];
    __syncthreads();
    __nv_bfloat16* Hh_ = g_Wthi + (size_t)z * Dd * Dd;
    __nv_bfloat16* Ll_ = g_Wtlo + (size_t)z * Dd * Dd;
#pragma unroll
    for (int i = 0; i < 4; i++) {
        float v = t[tx][ty + i * 8];                           // t[k_local][n_local]
        __nv_bfloat16 h = __float2bfloat16(v);
        __nv_bfloat16 l = __float2bfloat16(v - __bfloat162float(h));
        size_t idx = (size_t)(n0 + ty + i * 8) * Dd + k0 + tx;
        Hh_[idx] = h;
        Ll_[idx] = l;
    }
}

// ================= HMMA GEMM: C = A @ W + bias =============================
// A hi/lo bf16 [M,K]; Wt hi/lo bf16 [N,K] (K-major == col-major for mma).
// 128x128 CTA tile, 8 warps (2m x 4n), warp tile 64x32 = 4x4 m16n8k16.
// K chunks of 64, double-buffered cp.async into SW128-swizzled smem,
// 3 split products (hi*hi + hi*lo + lo*hi) into fp32 accumulators.
#define GEMM_SMEM (2*4*16384 + 1024)

__global__ void __launch_bounds__(256, 1)
tc_gemm(const __nv_bfloat16* __restrict__ Ahi, const __nv_bfloat16* __restrict__ Alo,
        int wbase,
        const float* b0p, const float* b1p, const float* b2p, const float* b3p,
        float* c0, float* c1, float* c2, float* c3)
{
    extern __shared__ char dsm[];
    const int z = blockIdx.z;
    const float* bias = (z == 0) ? b0p : (z == 1) ? b1p : (z == 2) ? b2p : b3p;
    float* C          = (z == 0) ? c0 : (z == 1) ? c1 : (z == 2) ? c2 : c3;
    const __nv_bfloat16* Bhi = g_Wthi + (size_t)(wbase + z) * Dd * Dd;
    const __nv_bfloat16* Blo = g_Wtlo + (size_t)(wbase + z) * Dd * Dd;

    const int m0 = blockIdx.y * 128, n0 = blockIdx.x * 128;
    const int tid = threadIdx.x;
    const int w = tid >> 5, lane = tid & 31;
    const int wm = (w & 1) * 64;        // warp m origin within tile
    const int wn = (w >> 1) * 32;       // warp n origin within tile

    uint32_t sb = (s2u(dsm) + 1023) & ~1023u;

    // loader: thread copies 4 consecutive 16B units in one row segment / tile
    const int v0 = tid * 4;
    const int row = v0 >> 3;            // 0..127
    const int cu = v0 & 7;              // 0 or 4
    const size_t offA = (size_t)(m0 + row) * Dd + cu * 8;
    const size_t offB = (size_t)(n0 + row) * Dd + cu * 8;
    const uint32_t so = row * 128 + cu * 16;

#define LOAD_CHUNK(c) do {                                                     \
    const uint32_t tb = sb + ((c) & 1) * 65536;                                \
    const int kc = (c) * 64;                                                   \
    _Pragma("unroll")                                                          \
    for (int u = 0; u < 4; u++) {                                              \
        uint32_t d = SWZ(so + u * 16);                                         \
        const __nv_bfloat16* sa = Ahi + offA + kc + u * 8;                     \
        CP16(tb + d,          (size_t)__cvta_generic_to_global(sa));           \
        sa = Alo + offA + kc + u * 8;                                          \
        CP16(tb + 16384 + d,  (size_t)__cvta_generic_to_global(sa));           \
        sa = Bhi + offB + kc + u * 8;                                          \
        CP16(tb + 32768 + d,  (size_t)__cvta_generic_to_global(sa));           \
        sa = Blo + offB + kc + u * 8;                                          \
        CP16(tb + 49152 + d,  (size_t)__cvta_generic_to_global(sa));           \
    }                                                                          \
    CPCOMMIT();                                                                \
} while (0)

    float acc[4][4][4];
#pragma unroll
    for (int mt = 0; mt < 4; mt++)
#pragma unroll
        for (int nt = 0; nt < 4; nt++)
#pragma unroll
            for (int e = 0; e < 4; e++) acc[mt][nt][e] = 0.f;

    // ldmatrix per-thread address components (x4: rows t%16, k-half t/16)
    const int trow = lane & 15;
    const int thalf = lane >> 4;

    LOAD_CHUNK(0);

    for (int c = 0; c < 16; c++) {
        if (c < 15) { LOAD_CHUNK(c + 1); CPWAIT1(); } else { CPWAIT0(); }
        __syncthreads();

        const uint32_t tb = sb + (c & 1) * 65536;
#pragma unroll
        for (int ks = 0; ks < 4; ks++) {
            const uint32_t kb = ks * 32 + thalf * 16;
            uint32_t ahf[4][4], alf[4][4], bhf[2][4], blf[2][4];
#pragma unroll
            for (int mt = 0; mt < 4; mt++) {
                uint32_t off = SWZ((uint32_t)(wm + mt * 16 + trow) * 128 + kb);
                LDSM4(ahf[mt], tb + off);
                LDSM4(alf[mt], tb + 16384 + off);
            }
#pragma unroll
            for (int bt = 0; bt < 2; bt++) {
                uint32_t off = SWZ((uint32_t)(wn + bt * 16 + trow) * 128 + kb);
                LDSM4(bhf[bt], tb + 32768 + off);
                LDSM4(blf[bt], tb + 49152 + off);
            }
#pragma unroll
            for (int mt = 0; mt < 4; mt++)
#pragma unroll
                for (int nt = 0; nt < 4; nt++) {
                    const int g = nt >> 1, s = nt & 1;
                    mma_bf16(acc[mt][nt], ahf[mt], bhf[g][s], bhf[g][s + 2]);
                    mma_bf16(acc[mt][nt], ahf[mt], blf[g][s], blf[g][s + 2]);
                    mma_bf16(acc[mt][nt], alf[mt], bhf[g][s], bhf[g][s + 2]);
                }
        }
        __syncthreads();
    }

    // epilogue: acc[mt][nt]: c0,c1 -> (row = mt*16 + lane/4, col = nt*8 + (lane%4)*2)
    //                        c2,c3 -> row + 8
    const int erow = lane >> 2;
    const int ecol = (lane & 3) * 2;
#pragma unroll
    for (int nt = 0; nt < 4; nt++) {
        const int gcol = n0 + wn + nt * 8 + ecol;
        const float bx = bias[gcol], by = bias[gcol + 1];
#pragma unroll
        for (int mt = 0; mt < 4; mt++) {
            const int grow = m0 + wm + mt * 16 + erow;
            float2 o0 = make_float2(acc[mt][nt][0] + bx, acc[mt][nt][1] + by);
            float2 o1 = make_float2(acc[mt][nt][2] + bx, acc[mt][nt][3] + by);
            *reinterpret_cast<float2*>(&C[(size_t)grow * Dd + gcol])       = o0;
            *reinterpret_cast<float2*>(&C[(size_t)(grow + 8) * Dd + gcol]) = o1;
        }
    }
}

// ---------------- gate: sigmoid(gelu(G1) @ Wg2 + bg2) ---------------------
__global__ void __launch_bounds__(128) gate_kernel(
    const float* __restrict__ G1, const float* __restrict__ Wg2,
    const float* __restrict__ bg2, float* __restrict__ gate)
{
    const int row = blockIdx.x;
    const int tid = threadIdx.x;
    float s = 0.f;
#pragma unroll 4
    for (int k = tid; k < Dd; k += 128) {
        float v = G1[(size_t)row * Dd + k];
        float g = 0.5f * v * (1.0f + erff(v * 0.70710678118654752440f));
        s += g * Wg2[k];
    }
    __shared__ float red[128];
    red[tid] = s;
    __syncthreads();
    for (int off = 64; off; off >>= 1) {
        if (tid < off) red[tid] += red[tid + off];
        __syncthreads();
    }
    if (tid == 0) gate[row] = 1.0f / (1.0f + expf(-(red[0] + bg2[0])));
}

// ---------------- attention: block per (b, h, 64-query tile) --------------
#define SS_STRIDE 65
#define ATTN_SMEM ((64*64 + 64*64 + 64*SS_STRIDE) * 4)

__global__ void __launch_bounds__(256) attn_kernel(
    const float* __restrict__ Q, const float* __restrict__ K,
    const float* __restrict__ V, const float* __restrict__ gate,
    float* __restrict__ core, float* __restrict__ ent_out)
{
    extern __shared__ float sm[];
    float* QT = sm;              // [64][64] q transposed
    float* KT = sm + 4096;       // K transposed (pass1) / V natural (pass2)
    float* Ss = sm + 8192;       // [64][SS_STRIDE] probabilities

    const int qt = blockIdx.x, h = blockIdx.y, b = blockIdx.z;
    const int tid = threadIdx.x;
    const int tx = tid & 15, ty = tid >> 4;
    const int q0 = qt * 64;
    const int hoff = h * DH;
    const int rowbase = b * Nn;
    const size_t headbase = ((size_t)(b * Hh + h) * TILE_PAIRS + (size_t)qt * (qt + 1) / 2) * 4096;

    const int lr = tid >> 2;
    const int lc = (tid & 3) * 16;

    {
        const float* src = &Q[(size_t)(rowbase + q0 + lr) * Dd + hoff + lc];
#pragma unroll
        for (int j = 0; j < 16; j += 4) {
            float4 v = *reinterpret_cast<const float4*>(src + j);
            QT[(lc + j + 0) * 64 + lr] = v.x;
            QT[(lc + j + 1) * 64 + lr] = v.y;
            QT[(lc + j + 2) * 64 + lr] = v.z;
            QT[(lc + j + 3) * 64 + lr] = v.w;
        }
    }

    float mrow[4], Zrow[4];
#pragma unroll
    for (int i = 0; i < 4; i++) { mrow[i] = -1e30f; Zrow[i] = 0.f; }

    // ===== PASS 1: scores -> g_S, running max & Z =====
    for (int kt = 0; kt <= qt; kt++) {
        {
            const float* src = &K[(size_t)(rowbase + kt * 64 + lr) * Dd + hoff + lc];
#pragma unroll
            for (int j = 0; j < 16; j += 4) {
                float4 v = *reinterpret_cast<const float4*>(src + j);
                KT[(lc + j + 0) * 64 + lr] = v.x;
                KT[(lc + j + 1) * 64 + lr] = v.y;
                KT[(lc + j + 2) * 64 + lr] = v.z;
                KT[(lc + j + 3) * 64 + lr] = v.w;
            }
        }
        __syncthreads();

        float s[4][4];
#pragma unroll
        for (int i = 0; i < 4; i++)
#pragma unroll
            for (int j = 0; j < 4; j++) s[i][j] = 0.f;
#pragma unroll 16
        for (int d = 0; d < 64; d++) {
            float4 qv = *reinterpret_cast<const float4*>(&QT[d * 64 + ty * 4]);
            float4 kv = *reinterpret_cast<const float4*>(&KT[d * 64 + tx * 4]);
            float qa[4] = {qv.x, qv.y, qv.z, qv.w};
            float ka[4] = {kv.x, kv.y, kv.z, kv.w};
#pragma unroll
            for (int i = 0; i < 4; i++)
#pragma unroll
                for (int j = 0; j < 4; j++) s[i][j] += qa[i] * ka[j];
        }

        const bool diag = (kt == qt);
        float* Sg = &g_S[headbase + (size_t)kt * 4096];
#pragma unroll
        for (int i = 0; i < 4; i++) {
            const int qi = q0 + ty * 4 + i;
#pragma unroll
            for (int j = 0; j < 4; j++) {
                float v = s[i][j] * SCALE;
                if (diag && (kt * 64 + tx * 4 + j) > qi) v = -1e30f;
                s[i][j] = v;
            }
            float4 sv = make_float4(s[i][0], s[i][1], s[i][2], s[i][3]);
            *reinterpret_cast<float4*>(&Sg[(ty * 4 + i) * 64 + tx * 4]) = sv;

            float tm = fmaxf(fmaxf(s[i][0], s[i][1]), fmaxf(s[i][2], s[i][3]));
#pragma unroll
            for (int off = 8; off; off >>= 1)
                tm = fmaxf(tm, __shfl_xor_sync(0xffffffffu, tm, off, 16));
            float nm = fmaxf(mrow[i], tm);
            float es = __expf(s[i][0] - nm) + __expf(s[i][1] - nm) +
                       __expf(s[i][2] - nm) + __expf(s[i][3] - nm);
#pragma unroll
            for (int off = 8; off; off >>= 1)
                es += __shfl_xor_sync(0xffffffffu, es, off, 16);
            Zrow[i] = Zrow[i] * __expf(mrow[i] - nm) + es;
            mrow[i] = nm;
        }
        __syncthreads();
    }

    float invZ[4], entAcc[4], o[4][4];
#pragma unroll
    for (int i = 0; i < 4; i++) {
        invZ[i] = 1.0f / Zrow[i];
        entAcc[i] = 0.f;
#pragma unroll
        for (int j = 0; j < 4; j++) o[i][j] = 0.f;
    }

    // ===== PASS 2: reload S, exact p, entropy, PV =====
    for (int kt = 0; kt <= qt; kt++) {
        const float* Sg = &g_S[headbase + (size_t)kt * 4096];
#pragma unroll
        for (int i = 0; i < 4; i++) {
            float4 sv = *reinterpret_cast<const float4*>(&Sg[(ty * 4 + i) * 64 + tx * 4]);
            float sr[4] = {sv.x, sv.y, sv.z, sv.w};
#pragma unroll
            for (int j = 0; j < 4; j++) {
                float p = __expf(sr[j] - mrow[i]) * invZ[i];
                entAcc[i] -= p * logf(p + 1e-6f);
                Ss[(ty * 4 + i) * SS_STRIDE + tx * 4 + j] = p;
            }
        }

        {
            const float* src = &V[(size_t)(rowbase + kt * 64 + lr) * Dd + hoff + lc];
#pragma unroll
            for (int j = 0; j < 16; j += 4) {
                *reinterpret_cast<float4*>(&KT[lr * 64 + lc + j]) =
                    *reinterpret_cast<const float4*>(src + j);
            }
        }
        __syncthreads();

#pragma unroll 8
        for (int k = 0; k < 64; k++) {
            float pa[4];
#pragma unroll
            for (int i = 0; i < 4; i++) pa[i] = Ss[(ty * 4 + i) * SS_STRIDE + k];
            float4 vv = *reinterpret_cast<const float4*>(&KT[k * 64 + tx * 4]);
            float va[4] = {vv.x, vv.y, vv.z, vv.w};
#pragma unroll
            for (int i = 0; i < 4; i++)
#pragma unroll
                for (int j = 0; j < 4; j++) o[i][j] += pa[i] * va[j];
        }
        __syncthreads();
    }

#pragma unroll
    for (int i = 0; i < 4; i++) {
        float e = entAcc[i];
#pragma unroll
        for (int off = 8; off; off >>= 1)
            e += __shfl_xor_sync(0xffffffffu, e, off, 16);
        if (tx == 0)
            ent_out[((size_t)(b * Hh + h)) * Nn + q0 + ty * 4 + i] = e;
    }
#pragma unroll
    for (int i = 0; i < 4; i++) {
        const int qi = q0 + ty * 4 + i;
        const float g = gate[rowbase + qi];
        float4 ov;
        ov.x = o[i][0] * g; ov.y = o[i][1] * g;
        ov.z = o[i][2] * g; ov.w = o[i][3] * g;
        *reinterpret_cast<float4*>(&core[(size_t)(rowbase + qi) * Dd + hoff + tx * 4]) = ov;
    }
}

// ---------------- launch ----------------
extern "C" void kernel_launch(void* const* d_in, const int* in_sizes, int n_in,
                              void* d_out, int out_size)
{
    const float* x   = (const float*)d_in[0];
    // d_in[1] = attn_bias (pure causal; implemented analytically)
    const float* Wq  = (const float*)d_in[2];
    const float* bq  = (const float*)d_in[3];
    const float* Wk  = (const float*)d_in[4];
    const float* bk  = (const float*)d_in[5];
    const float* Wv  = (const float*)d_in[6];
    const float* bv  = (const float*)d_in[7];
    const float* Wg1 = (const float*)d_in[8];
    const float* bg1 = (const float*)d_in[9];
    const float* Wg2 = (const float*)d_in[10];
    const float* bg2 = (const float*)d_in[11];
    const float* Wo  = (const float*)d_in[12];
    const float* bo  = (const float*)d_in[13];

    float* out = (float*)d_out;                        // [B,N,D]
    float* ent = out + (size_t)Bb * Nn * Dd;           // [B,H,N]

    float *Qp, *Kp, *Vp, *G1p, *gp, *cp;
    __nv_bfloat16 *ahp, *alp;
    cudaGetSymbolAddress((void**)&Qp,  g_Q);
    cudaGetSymbolAddress((void**)&Kp,  g_K);
    cudaGetSymbolAddress((void**)&Vp,  g_V);
    cudaGetSymbolAddress((void**)&G1p, g_G1);
    cudaGetSymbolAddress((void**)&gp,  g_gate);
    cudaGetSymbolAddress((void**)&cp,  g_core);
    cudaGetSymbolAddress((void**)&ahp, g_Ahi);
    cudaGetSymbolAddress((void**)&alp, g_Alo);

    cudaFuncSetAttribute(tc_gemm,
        cudaFuncAttributeMaxDynamicSharedMemorySize, GEMM_SMEM);
    cudaFuncSetAttribute(attn_kernel,
        cudaFuncAttributeMaxDynamicSharedMemorySize, ATTN_SMEM);

    // weights -> transposed bf16 hi/lo (order: Wq, Wk, Wv, Wg1, Wo)
    wsplit_kernel<<<dim3(32, 32, 5), 256>>>(Wq, Wk, Wv, Wg1, Wo);
    // x -> bf16 hi/lo
    asplit_kernel<<<(MR * Dd) / 1024, 256>>>(x, ahp, alp);

    // fused Q/K/V/G1 projections on tensor cores (HMMA)
    tc_gemm<<<dim3(Dd / 128, MR / 128, 4), 256, GEMM_SMEM>>>(
        ahp, alp, 0, bq, bk, bv, bg1, Qp, Kp, Vp, G1p);

    gate_kernel<<<MR, 128>>>(G1p, Wg2, bg2, gp);

    attn_kernel<<<dim3(Nn / 64, Hh, Bb), 256, ATTN_SMEM>>>(Qp, Kp, Vp, gp, cp, ent);

    // core -> bf16 hi/lo, then output projection
    asplit_kernel<<<(MR * Dd) / 1024, 256>>>(cp, ahp, alp);
    tc_gemm<<<dim3(Dd / 128, MR / 128, 1), 256, GEMM_SMEM>>>(
        ahp, alp, 4, bo, bo, bo, bo, out, out, out, out);
}